// round 3
// baseline (speedup 1.0000x reference)
#include <cuda_runtime.h>
#include <cuda_bf16.h>
#include <math.h>

#define NN 80000
#define EE 1280000
#define DHID 64
#define DOUT_FINAL 40
#define NB_SCAN 79   // ceil(80000/1024)

// ---------------- scratch (static device globals; no allocs) ----------------
__device__ float g_buf0[(size_t)NN * DHID];         // h0 fp32
__device__ float g_buf1[(size_t)NN * DHID];         // h1 fp32
__device__ __nv_bfloat16 g_bfA[(size_t)NN * DHID];  // bf16 ping
__device__ __nv_bfloat16 g_bfB[(size_t)NN * DHID];  // bf16 pong
__device__ float g_out3[(size_t)NN * DOUT_FINAL];   // logits
__device__ int   g_deg[NN];
__device__ float g_deginv[NN];
__device__ int   g_rowstart[NN + 1];
__device__ int   g_cursor[NN];
__device__ int   g_bsum[NB_SCAN];
__device__ int   g_csr[EE];                         // src indices grouped by dst
__device__ float g_acc[2];                          // {sum(nll*m), sum(m)}

// ---------------- init: zero deg/acc + convert x -> bf16 (fused) ----------------
__global__ void k_init(const float* __restrict__ x) {
    int i = blockIdx.x * blockDim.x + threadIdx.x;   // covers NN*16 float4 chunks
    if (i < NN * 16) {
        float4 v = __ldg((const float4*)x + i);
        __nv_bfloat162 a = __floats2bfloat162_rn(v.x, v.y);
        __nv_bfloat162 b = __floats2bfloat162_rn(v.z, v.w);
        uint2 u;
        u.x = *(unsigned*)&a; u.y = *(unsigned*)&b;
        ((uint2*)g_bfA)[i] = u;
    }
    if (i < NN) g_deg[i] = 0;
    if (i < 2)  g_acc[i] = 0.f;
}

__global__ void k_count_deg(const int* __restrict__ dst) {
    int e = blockIdx.x * blockDim.x + threadIdx.x;
    if (e < EE) atomicAdd(&g_deg[dst[e]], 1);
}

__global__ void __launch_bounds__(1024) k_scan1() {
    __shared__ int s[1024];
    int t = threadIdx.x;
    int i = blockIdx.x * 1024 + t;
    int v = (i < NN) ? g_deg[i] : 0;
    s[t] = v;
    __syncthreads();
    #pragma unroll
    for (int o = 1; o < 1024; o <<= 1) {
        int u = (t >= o) ? s[t - o] : 0;
        __syncthreads();
        s[t] += u;
        __syncthreads();
    }
    if (i < NN) g_rowstart[i] = s[t] - v;        // exclusive, chunk-local
    if (t == 1023) g_bsum[blockIdx.x] = s[t];
}

__global__ void __launch_bounds__(128) k_scan2() {
    __shared__ int s[128];
    int t = threadIdx.x;
    int v = (t < NB_SCAN) ? g_bsum[t] : 0;
    s[t] = v;
    __syncthreads();
    #pragma unroll
    for (int o = 1; o < 128; o <<= 1) {
        int u = (t >= o) ? s[t - o] : 0;
        __syncthreads();
        s[t] += u;
        __syncthreads();
    }
    if (t < NB_SCAN) g_bsum[t] = s[t] - v;       // exclusive
}

__global__ void k_scan3() {
    int i = blockIdx.x * blockDim.x + threadIdx.x;
    if (i < NN) {
        int rs = g_rowstart[i] + g_bsum[i >> 10];
        g_rowstart[i] = rs;
        g_cursor[i]   = rs;
        int d = g_deg[i];
        g_deginv[i] = (d > 0) ? 1.f / (float)d : 0.f;
    }
    if (i == 0) g_rowstart[NN] = EE;
}

__global__ void k_build(const int* __restrict__ dst, const int* __restrict__ src) {
    int e = blockIdx.x * blockDim.x + threadIdx.x;
    if (e < EE) {
        int d = dst[e];
        int slot = atomicAdd(&g_cursor[d], 1);
        g_csr[slot] = src[e];
    }
}

// ---------------- fused layer: gather (bf16) + SAGE linear ----------------
// Block: 256 threads, 64 nodes. out = act([aggr | h] @ [Wl^T; Wr^T] + bl+br)
template<bool RELU, bool WRITE_BF, int DOUT>
__global__ void __launch_bounds__(256) k_layer(
    const float* __restrict__ hin,            // fp32 activations (self path)
    const __nv_bfloat16* __restrict__ hbf,    // bf16 activations (neighbor path)
    const float* __restrict__ Wl, const float* __restrict__ bl,
    const float* __restrict__ Wr, const float* __restrict__ br,
    float* __restrict__ out, __nv_bfloat16* __restrict__ outbf)
{
    extern __shared__ float sm[];
    float* s_in = sm;                 // [64][129]  k<64: aggr, k>=64: h(self)
    float* s_w  = sm + 64 * 129;      // [128][64]
    float* s_b  = s_w + 128 * 64;     // [64]

    const int t  = threadIdx.x;
    const int nb = blockIdx.x * 64;

    // ---- stage weights (transposed + stacked, zero-padded) ----
    for (int i = t; i < 128 * 64; i += 256) {
        int k = i >> 6, d = i & 63;
        float w = 0.f;
        if (d < DOUT) w = (k < 64) ? __ldg(Wl + d * 64 + k) : __ldg(Wr + d * 64 + (k - 64));
        s_w[i] = w;
    }
    if (t < 64) s_b[t] = (t < DOUT) ? (__ldg(bl + t) + __ldg(br + t)) : 0.f;

    // ---- stage self rows (fp32) ----
    for (int i = t; i < 64 * 16; i += 256) {
        int n = i >> 4, c = i & 15;
        float4 v = __ldg((const float4*)(hin + (size_t)(nb + n) * 64) + c);
        float* p = s_in + n * 129 + 64 + c * 4;
        p[0] = v.x; p[1] = v.y; p[2] = v.z; p[3] = v.w;
    }

    // ---- gather: warp w handles nodes w*8..w*8+7 ----
    {
        const int w    = t >> 5;
        const int lane = t & 31;
        const int half = lane >> 4;
        const int c    = lane & 15;          // 4 dims: c*4..c*4+3
        for (int i = 0; i < 8; ++i) {
            int nl = w * 8 + i;
            int gn = nb + nl;
            int s0 = __ldg(g_rowstart + gn);
            int s1 = __ldg(g_rowstart + gn + 1);
            float a0 = 0.f, a1 = 0.f, a2 = 0.f, a3 = 0.f;
            for (int j = s0 + half; j < s1; j += 2) {
                int s = __ldg(g_csr + j);
                uint2 u = __ldg((const uint2*)(hbf + (size_t)s * 64) + c);
                float2 p0 = __bfloat1622float2(*(__nv_bfloat162*)&u.x);
                float2 p1 = __bfloat1622float2(*(__nv_bfloat162*)&u.y);
                a0 += p0.x; a1 += p0.y; a2 += p1.x; a3 += p1.y;
            }
            a0 += __shfl_down_sync(0xffffffffu, a0, 16);
            a1 += __shfl_down_sync(0xffffffffu, a1, 16);
            a2 += __shfl_down_sync(0xffffffffu, a2, 16);
            a3 += __shfl_down_sync(0xffffffffu, a3, 16);
            if (half == 0) {
                float di = __ldg(g_deginv + gn);
                float* p = s_in + nl * 129 + c * 4;
                p[0] = a0 * di; p[1] = a1 * di; p[2] = a2 * di; p[3] = a3 * di;
            }
        }
    }
    __syncthreads();

    // ---- GEMM: thread -> nodes {nq, nq+32} x dims dg*8..dg*8+7 ----
    const int nq = t & 31;
    const int dg = t >> 5;

    float acc[2][8];
    #pragma unroll
    for (int j = 0; j < 2; ++j)
        #pragma unroll
        for (int dd = 0; dd < 8; ++dd) acc[j][dd] = s_b[dg * 8 + dd];

    const float4* w4 = (const float4*)s_w;
    #pragma unroll 8
    for (int k = 0; k < 128; ++k) {
        float4 w0 = w4[k * 16 + dg * 2];
        float4 w1 = w4[k * 16 + dg * 2 + 1];
        float a0 = s_in[nq * 129 + k];
        float a1 = s_in[(nq + 32) * 129 + k];
        acc[0][0] += a0 * w0.x; acc[0][1] += a0 * w0.y;
        acc[0][2] += a0 * w0.z; acc[0][3] += a0 * w0.w;
        acc[0][4] += a0 * w1.x; acc[0][5] += a0 * w1.y;
        acc[0][6] += a0 * w1.z; acc[0][7] += a0 * w1.w;
        acc[1][0] += a1 * w0.x; acc[1][1] += a1 * w0.y;
        acc[1][2] += a1 * w0.z; acc[1][3] += a1 * w0.w;
        acc[1][4] += a1 * w1.x; acc[1][5] += a1 * w1.y;
        acc[1][6] += a1 * w1.z; acc[1][7] += a1 * w1.w;
    }

    #pragma unroll
    for (int j = 0; j < 2; ++j) {
        int n = nb + nq + j * 32;
        int d0 = dg * 8;
        if (d0 < DOUT) {
            float v[8];
            #pragma unroll
            for (int dd = 0; dd < 8; ++dd) {
                float z = acc[j][dd];
                v[dd] = RELU ? fmaxf(z, 0.f) : z;
            }
            float* po = out + (size_t)n * DOUT + d0;
            ((float4*)po)[0] = make_float4(v[0], v[1], v[2], v[3]);
            ((float4*)po)[1] = make_float4(v[4], v[5], v[6], v[7]);
            if (WRITE_BF) {
                __nv_bfloat162 b0 = __floats2bfloat162_rn(v[0], v[1]);
                __nv_bfloat162 b1 = __floats2bfloat162_rn(v[2], v[3]);
                __nv_bfloat162 b2 = __floats2bfloat162_rn(v[4], v[5]);
                __nv_bfloat162 b3 = __floats2bfloat162_rn(v[6], v[7]);
                uint4 u;
                u.x = *(unsigned*)&b0; u.y = *(unsigned*)&b1;
                u.z = *(unsigned*)&b2; u.w = *(unsigned*)&b3;
                *(uint4*)(outbf + (size_t)n * 64 + d0) = u;
            }
        }
    }
}

// ---------------- loss: masked mean NLL of log_softmax ----------------
__global__ void k_loss(const int* __restrict__ y, const int* __restrict__ mask) {
    int i = blockIdx.x * blockDim.x + threadIdx.x;
    float nll = 0.f, m = 0.f;
    if (i < NN && mask[i] != 0) {
        const float* l = g_out3 + (size_t)i * DOUT_FINAL;
        float mx = l[0];
        #pragma unroll
        for (int d = 1; d < DOUT_FINAL; ++d) mx = fmaxf(mx, l[d]);
        float s = 0.f;
        #pragma unroll
        for (int d = 0; d < DOUT_FINAL; ++d) s += expf(l[d] - mx);
        nll = mx + logf(s) - l[y[i]];
        m = 1.f;
    }
    #pragma unroll
    for (int o = 16; o > 0; o >>= 1) {
        nll += __shfl_down_sync(0xffffffffu, nll, o);
        m   += __shfl_down_sync(0xffffffffu, m, o);
    }
    if ((threadIdx.x & 31) == 0) {
        atomicAdd(&g_acc[0], nll);
        atomicAdd(&g_acc[1], m);
    }
}

__global__ void k_final(float* out) {
    out[0] = g_acc[0] / fmaxf(g_acc[1], 1.f);
}

// ---------------- launcher ----------------
extern "C" void kernel_launch(void* const* d_in, const int* in_sizes, int n_in,
                              void* d_out, int out_size) {
    const float* x   = (const float*)d_in[0];
    const float* Wl0 = (const float*)d_in[1];
    const float* bl0 = (const float*)d_in[2];
    const float* Wr0 = (const float*)d_in[3];
    const float* br0 = (const float*)d_in[4];
    const float* Wl1 = (const float*)d_in[5];
    const float* bl1 = (const float*)d_in[6];
    const float* Wr1 = (const float*)d_in[7];
    const float* br1 = (const float*)d_in[8];
    const float* Wl2 = (const float*)d_in[9];
    const float* bl2 = (const float*)d_in[10];
    const float* Wr2 = (const float*)d_in[11];
    const float* br2 = (const float*)d_in[12];
    const int*   ei  = (const int*)d_in[13];
    const int*   y   = (const int*)d_in[14];
    const int*   msk = (const int*)d_in[15];
    const int* dst = ei;        // edge_index[0]
    const int* src = ei + EE;   // edge_index[1]

    float *buf0, *buf1, *out3;
    __nv_bfloat16 *bfA, *bfB;
    cudaGetSymbolAddress((void**)&buf0, g_buf0);
    cudaGetSymbolAddress((void**)&buf1, g_buf1);
    cudaGetSymbolAddress((void**)&out3, g_out3);
    cudaGetSymbolAddress((void**)&bfA, g_bfA);
    cudaGetSymbolAddress((void**)&bfB, g_bfB);

    const int smem = (64 * 129 + 128 * 64 + 64) * (int)sizeof(float); // 66304 B
    cudaFuncSetAttribute(k_layer<true, true, 64>,   cudaFuncAttributeMaxDynamicSharedMemorySize, smem);
    cudaFuncSetAttribute(k_layer<false, false, 40>, cudaFuncAttributeMaxDynamicSharedMemorySize, smem);

    // CSR build + x->bf16
    k_init<<<(NN * 16 + 255) / 256, 256>>>(x);
    k_count_deg<<<(EE + 255) / 256, 256>>>(dst);
    k_scan1<<<NB_SCAN, 1024>>>();
    k_scan2<<<1, 128>>>();
    k_scan3<<<(NN + 255) / 256, 256>>>();
    k_build<<<(EE + 255) / 256, 256>>>(dst, src);

    const int gemm_blocks = NN / 64;   // 1250

    // layer 0: (x, bfA) -> (buf0, bfB)
    k_layer<true, true, 64><<<gemm_blocks, 256, smem>>>(x, bfA, Wl0, bl0, Wr0, br0, buf0, bfB);
    // layer 1: (buf0, bfB) -> (buf1, bfA)
    k_layer<true, true, 64><<<gemm_blocks, 256, smem>>>(buf0, bfB, Wl1, bl1, Wr1, br1, buf1, bfA);
    // layer 2: (buf1, bfA) -> out3 (40 dims, no relu, no bf out)
    k_layer<false, false, 40><<<gemm_blocks, 256, smem>>>(buf1, bfA, Wl2, bl2, Wr2, br2, out3, nullptr);

    k_loss<<<(NN + 255) / 256, 256>>>(y, msk);
    k_final<<<1, 1>>>((float*)d_out);
}

// round 4
// speedup vs baseline: 2.5792x; 2.5792x over previous
#include <cuda_runtime.h>
#include <cuda_bf16.h>
#include <math.h>
#include <stdint.h>

#define NN 80000
#define EE 1280000
#define DOUT_FINAL 40
#define NB_SCAN 79   // ceil(80000/1024)
#define STRIDE 136   // smem row stride in bf16 elems (conflict-free for mma loads)

// ---------------- scratch (static device globals; no allocs) ----------------
__device__ __nv_bfloat16 g_bfA[(size_t)NN * 64];
__device__ __nv_bfloat16 g_bfB[(size_t)NN * 64];
__device__ __nv_bfloat16 g_wbf[3][64 * 128];   // stacked [Wl^T;Wr^T] as [n][k]
__device__ float g_bias[3][64];
__device__ float g_out3[(size_t)NN * DOUT_FINAL];
__device__ int   g_deg[NN];
__device__ float g_deginv[NN];
__device__ int   g_rowstart[NN + 1];
__device__ int   g_cursor[NN];
__device__ int   g_bsum[NB_SCAN];
__device__ int   g_csr[EE];
__device__ float g_acc[2];

// ---------------- preamble ----------------
__global__ void k_zero() {
    int i = blockIdx.x * blockDim.x + threadIdx.x;
    if (i < NN) g_deg[i] = 0;
    if (i < 2)  g_acc[i] = 0.f;
}

// fused: x->bf16, degree count, weights/bias -> bf16 stacked
__global__ void k_init(const float* __restrict__ x, const int* __restrict__ dst,
                       const float* __restrict__ Wl0, const float* __restrict__ bl0,
                       const float* __restrict__ Wr0, const float* __restrict__ br0,
                       const float* __restrict__ Wl1, const float* __restrict__ bl1,
                       const float* __restrict__ Wr1, const float* __restrict__ br1,
                       const float* __restrict__ Wl2, const float* __restrict__ bl2,
                       const float* __restrict__ Wr2, const float* __restrict__ br2) {
    int i = blockIdx.x * blockDim.x + threadIdx.x;   // 1,280,000 threads
    if (i < NN * 16) {
        float4 v = __ldg((const float4*)x + i);
        __nv_bfloat162 a = __floats2bfloat162_rn(v.x, v.y);
        __nv_bfloat162 b = __floats2bfloat162_rn(v.z, v.w);
        uint2 u;
        u.x = *(unsigned*)&a; u.y = *(unsigned*)&b;
        ((uint2*)g_bfA)[i] = u;
    }
    if (i < EE) atomicAdd(&g_deg[__ldg(dst + i)], 1);
    if (i < 3 * 64 * 128) {
        int l = i >> 13, r = i & 8191, n = r >> 7, k = r & 127;
        float w = 0.f;
        if (l == 0)      w = (k < 64) ? __ldg(Wl0 + n * 64 + k) : __ldg(Wr0 + n * 64 + k - 64);
        else if (l == 1) w = (k < 64) ? __ldg(Wl1 + n * 64 + k) : __ldg(Wr1 + n * 64 + k - 64);
        else if (n < DOUT_FINAL)
                         w = (k < 64) ? __ldg(Wl2 + n * 64 + k) : __ldg(Wr2 + n * 64 + k - 64);
        g_wbf[l][n * 128 + k] = __float2bfloat16(w);
    }
    if (i < 3 * 64) {
        int l = i >> 6, n = i & 63;
        float b = 0.f;
        if (l == 0)      b = __ldg(bl0 + n) + __ldg(br0 + n);
        else if (l == 1) b = __ldg(bl1 + n) + __ldg(br1 + n);
        else if (n < DOUT_FINAL) b = __ldg(bl2 + n) + __ldg(br2 + n);
        g_bias[l][n] = b;
    }
}

__global__ void __launch_bounds__(1024) k_scan1() {
    __shared__ int s[1024];
    int t = threadIdx.x;
    int i = blockIdx.x * 1024 + t;
    int v = (i < NN) ? g_deg[i] : 0;
    s[t] = v;
    __syncthreads();
    #pragma unroll
    for (int o = 1; o < 1024; o <<= 1) {
        int u = (t >= o) ? s[t - o] : 0;
        __syncthreads();
        s[t] += u;
        __syncthreads();
    }
    if (i < NN) g_rowstart[i] = s[t] - v;        // exclusive, chunk-local
    if (t == 1023) g_bsum[blockIdx.x] = s[t];
}

// fused scan2+scan3: per-block chunk-offset reduction + finalize
__global__ void __launch_bounds__(256) k_scan3() {
    __shared__ int s_off;
    int chunk = blockIdx.x >> 2;     // block covers 256 idx inside one 1024-chunk
    if (threadIdx.x < 32) {
        int v = 0;
        for (int b = threadIdx.x; b < chunk; b += 32) v += g_bsum[b];
        #pragma unroll
        for (int o = 16; o > 0; o >>= 1) v += __shfl_down_sync(0xffffffffu, v, o);
        if (threadIdx.x == 0) s_off = v;
    }
    __syncthreads();
    int i = blockIdx.x * 256 + threadIdx.x;
    if (i < NN) {
        int rs = g_rowstart[i] + s_off;
        g_rowstart[i] = rs;
        g_cursor[i]   = rs;
        int d = g_deg[i];
        g_deginv[i] = (d > 0) ? 1.f / (float)d : 0.f;
    }
    if (i == 0) g_rowstart[NN] = EE;
}

__global__ void k_build(const int* __restrict__ dst, const int* __restrict__ src) {
    int e = blockIdx.x * blockDim.x + threadIdx.x;
    if (e < EE) {
        int d = __ldg(dst + e);
        int slot = atomicAdd(&g_cursor[d], 1);
        g_csr[slot] = __ldg(src + e);
    }
}

// ---------------- fused layer: bf16 gather + HMMA transform ----------------
__device__ __forceinline__ void add8(float* a, uint4 u) {
    float2 p0 = __bfloat1622float2(*(__nv_bfloat162*)&u.x);
    float2 p1 = __bfloat1622float2(*(__nv_bfloat162*)&u.y);
    float2 p2 = __bfloat1622float2(*(__nv_bfloat162*)&u.z);
    float2 p3 = __bfloat1622float2(*(__nv_bfloat162*)&u.w);
    a[0] += p0.x; a[1] += p0.y; a[2] += p1.x; a[3] += p1.y;
    a[4] += p2.x; a[5] += p2.y; a[6] += p3.x; a[7] += p3.y;
}

__device__ __forceinline__ void mma16816(float& c0, float& c1, float& c2, float& c3,
                                         uint32_t a0, uint32_t a1, uint32_t a2, uint32_t a3,
                                         uint32_t b0, uint32_t b1) {
    asm volatile("mma.sync.aligned.m16n8k16.row.col.f32.bf16.bf16.f32 "
                 "{%0,%1,%2,%3}, {%4,%5,%6,%7}, {%8,%9}, {%0,%1,%2,%3};"
                 : "+f"(c0), "+f"(c1), "+f"(c2), "+f"(c3)
                 : "r"(a0), "r"(a1), "r"(a2), "r"(a3), "r"(b0), "r"(b1));
}

template<bool RELU, bool LAST>
__global__ void __launch_bounds__(256) k_layer(
    const __nv_bfloat16* __restrict__ hbf,   // input activations (bf16)
    const __nv_bfloat16* __restrict__ wbf,   // [64][128] stacked weights
    const float* __restrict__ bias,          // [64] bl+br
    __nv_bfloat16* __restrict__ outbf,       // next-layer activations (if !LAST)
    float* __restrict__ outf)                // logits (if LAST)
{
    __shared__ __nv_bfloat16 s_act[64 * STRIDE];  // [node][k]  k<64 aggr, k>=64 self
    __shared__ __nv_bfloat16 s_w[64 * STRIDE];    // [n][k]
    __shared__ float s_b[64];

    const int t  = threadIdx.x;
    const int nb = blockIdx.x * 64;

    // stage weights (uint4 = 8 bf16)
    #pragma unroll
    for (int idx = t; idx < 1024; idx += 256) {
        int n = idx >> 4, c = idx & 15;
        *(uint4*)(s_w + n * STRIDE + c * 8) = __ldg((const uint4*)(wbf + n * 128) + c);
    }
    if (t < 64) s_b[t] = __ldg(bias + t);

    // stage self rows into k = 64..127
    #pragma unroll
    for (int idx = t; idx < 512; idx += 256) {
        int n = idx >> 3, c = idx & 7;
        *(uint4*)(s_act + n * STRIDE + 64 + c * 8) =
            __ldg((const uint4*)(hbf + (size_t)(nb + n) * 64) + c);
    }

    // gather: warp w -> nodes w*8..w*8+7; quarter-warp per neighbor (MLP 4-8)
    {
        const int w    = t >> 5;
        const int lane = t & 31;
        const int q    = lane >> 3;     // neighbor slot 0..3
        const int d8   = lane & 7;      // dims d8*8..d8*8+7
        for (int i = 0; i < 8; ++i) {
            int nl = w * 8 + i;
            int gn = nb + nl;
            int s0 = __ldg(g_rowstart + gn);
            int s1 = __ldg(g_rowstart + gn + 1);
            float a[8] = {0.f, 0.f, 0.f, 0.f, 0.f, 0.f, 0.f, 0.f};
            int j = s0 + q;
            while (j + 4 < s1) {
                int i0 = __ldg(g_csr + j);
                int i1 = __ldg(g_csr + j + 4);
                uint4 u0 = __ldg((const uint4*)(hbf + (size_t)i0 * 64) + d8);
                uint4 u1 = __ldg((const uint4*)(hbf + (size_t)i1 * 64) + d8);
                add8(a, u0);
                add8(a, u1);
                j += 8;
            }
            if (j < s1) {
                int i0 = __ldg(g_csr + j);
                uint4 u0 = __ldg((const uint4*)(hbf + (size_t)i0 * 64) + d8);
                add8(a, u0);
            }
            // fold 4 quarters
            #pragma unroll
            for (int v = 0; v < 8; ++v) a[v] += __shfl_xor_sync(0xffffffffu, a[v], 8);
            #pragma unroll
            for (int v = 0; v < 8; ++v) a[v] += __shfl_xor_sync(0xffffffffu, a[v], 16);
            if (q == 0) {
                float di = __ldg(g_deginv + gn);
                __nv_bfloat162 p0 = __floats2bfloat162_rn(a[0] * di, a[1] * di);
                __nv_bfloat162 p1 = __floats2bfloat162_rn(a[2] * di, a[3] * di);
                __nv_bfloat162 p2 = __floats2bfloat162_rn(a[4] * di, a[5] * di);
                __nv_bfloat162 p3 = __floats2bfloat162_rn(a[6] * di, a[7] * di);
                uint4 u;
                u.x = *(unsigned*)&p0; u.y = *(unsigned*)&p1;
                u.z = *(unsigned*)&p2; u.w = *(unsigned*)&p3;
                *(uint4*)(s_act + nl * STRIDE + d8 * 8) = u;
            }
        }
    }
    __syncthreads();

    // HMMA: warp -> m16 x n32 tile; 8 warps cover 64x64
    {
        const int w    = t >> 5;
        const int lane = t & 31;
        const int mw = (w & 3) * 16;
        const int nw = (w >> 2) * 32;
        const int g  = lane >> 2;       // row/col group
        const int tg = lane & 3;

        float c[4][4];
        #pragma unroll
        for (int nt = 0; nt < 4; ++nt) {
            int n0 = nw + nt * 8 + 2 * tg;
            c[nt][0] = s_b[n0]; c[nt][1] = s_b[n0 + 1];
            c[nt][2] = c[nt][0]; c[nt][3] = c[nt][1];
        }

        #pragma unroll
        for (int kk = 0; kk < 8; ++kk) {
            int k0 = kk * 16;
            const __nv_bfloat16* pa = s_act + (mw + g) * STRIDE + k0 + 2 * tg;
            uint32_t a0 = *(const uint32_t*)pa;
            uint32_t a1 = *(const uint32_t*)(pa + 8 * STRIDE);
            uint32_t a2 = *(const uint32_t*)(pa + 8);
            uint32_t a3 = *(const uint32_t*)(pa + 8 * STRIDE + 8);
            #pragma unroll
            for (int nt = 0; nt < 4; ++nt) {
                const __nv_bfloat16* pb = s_w + (nw + nt * 8 + g) * STRIDE + k0 + 2 * tg;
                uint32_t b0 = *(const uint32_t*)pb;
                uint32_t b1 = *(const uint32_t*)(pb + 8);
                mma16816(c[nt][0], c[nt][1], c[nt][2], c[nt][3], a0, a1, a2, a3, b0, b1);
            }
        }

        // epilogue
        #pragma unroll
        for (int nt = 0; nt < 4; ++nt) {
            int n0 = nw + nt * 8 + 2 * tg;
            int m0 = nb + mw + g;
            float v0 = c[nt][0], v1 = c[nt][1], v2 = c[nt][2], v3 = c[nt][3];
            if (RELU) {
                v0 = fmaxf(v0, 0.f); v1 = fmaxf(v1, 0.f);
                v2 = fmaxf(v2, 0.f); v3 = fmaxf(v3, 0.f);
            }
            if (LAST) {
                if (n0 < DOUT_FINAL) {
                    *(float2*)(outf + (size_t)m0 * DOUT_FINAL + n0) = make_float2(v0, v1);
                    *(float2*)(outf + (size_t)(m0 + 8) * DOUT_FINAL + n0) = make_float2(v2, v3);
                }
            } else {
                __nv_bfloat162 p0 = __floats2bfloat162_rn(v0, v1);
                __nv_bfloat162 p1 = __floats2bfloat162_rn(v2, v3);
                *(__nv_bfloat162*)(outbf + (size_t)m0 * 64 + n0) = p0;
                *(__nv_bfloat162*)(outbf + (size_t)(m0 + 8) * 64 + n0) = p1;
            }
        }
    }
}

// ---------------- loss ----------------
__global__ void k_loss(const int* __restrict__ y, const int* __restrict__ mask) {
    int i = blockIdx.x * blockDim.x + threadIdx.x;
    float nll = 0.f, m = 0.f;
    if (i < NN && mask[i] != 0) {
        const float* l = g_out3 + (size_t)i * DOUT_FINAL;
        float mx = l[0];
        #pragma unroll
        for (int d = 1; d < DOUT_FINAL; ++d) mx = fmaxf(mx, l[d]);
        float s = 0.f;
        #pragma unroll
        for (int d = 0; d < DOUT_FINAL; ++d) s += expf(l[d] - mx);
        nll = mx + logf(s) - l[y[i]];
        m = 1.f;
    }
    #pragma unroll
    for (int o = 16; o > 0; o >>= 1) {
        nll += __shfl_down_sync(0xffffffffu, nll, o);
        m   += __shfl_down_sync(0xffffffffu, m, o);
    }
    if ((threadIdx.x & 31) == 0) {
        atomicAdd(&g_acc[0], nll);
        atomicAdd(&g_acc[1], m);
    }
}

__global__ void k_final(float* out) {
    out[0] = g_acc[0] / fmaxf(g_acc[1], 1.f);
}

// ---------------- launcher ----------------
extern "C" void kernel_launch(void* const* d_in, const int* in_sizes, int n_in,
                              void* d_out, int out_size) {
    const float* x   = (const float*)d_in[0];
    const float* Wl0 = (const float*)d_in[1];
    const float* bl0 = (const float*)d_in[2];
    const float* Wr0 = (const float*)d_in[3];
    const float* br0 = (const float*)d_in[4];
    const float* Wl1 = (const float*)d_in[5];
    const float* bl1 = (const float*)d_in[6];
    const float* Wr1 = (const float*)d_in[7];
    const float* br1 = (const float*)d_in[8];
    const float* Wl2 = (const float*)d_in[9];
    const float* bl2 = (const float*)d_in[10];
    const float* Wr2 = (const float*)d_in[11];
    const float* br2 = (const float*)d_in[12];
    const int*   ei  = (const int*)d_in[13];
    const int*   y   = (const int*)d_in[14];
    const int*   msk = (const int*)d_in[15];
    const int* dst = ei;        // edge_index[0]
    const int* src = ei + EE;   // edge_index[1]

    __nv_bfloat16 *bfA, *bfB, *wbf;
    float *out3, *bias;
    cudaGetSymbolAddress((void**)&bfA, g_bfA);
    cudaGetSymbolAddress((void**)&bfB, g_bfB);
    cudaGetSymbolAddress((void**)&wbf, g_wbf);
    cudaGetSymbolAddress((void**)&out3, g_out3);
    cudaGetSymbolAddress((void**)&bias, g_bias);

    // preamble
    k_zero<<<(NN + 255) / 256, 256>>>();
    k_init<<<5000, 256>>>(x, dst, Wl0, bl0, Wr0, br0, Wl1, bl1, Wr1, br1, Wl2, bl2, Wr2, br2);
    k_scan1<<<NB_SCAN, 1024>>>();
    k_scan3<<<(NN + 255) / 256, 256>>>();
    k_build<<<(EE + 255) / 256, 256>>>(dst, src);

    const int blocks = NN / 64;   // 1250

    // layer 0: bfA -> bfB
    k_layer<true, false><<<blocks, 256>>>(bfA, wbf, bias, bfB, nullptr);
    // layer 1: bfB -> bfA
    k_layer<true, false><<<blocks, 256>>>(bfB, wbf + 64 * 128, bias + 64, bfA, nullptr);
    // layer 2: bfA -> out3
    k_layer<false, true><<<blocks, 256>>>(bfA, wbf + 2 * 64 * 128, bias + 128, nullptr, out3);

    k_loss<<<(NN + 255) / 256, 256>>>(y, msk);
    k_final<<<1, 1>>>((float*)d_out);
}

// round 5
// speedup vs baseline: 2.6086x; 1.0114x over previous
#include <cuda_runtime.h>
#include <cuda_bf16.h>
#include <math.h>
#include <stdint.h>

#define NN 80000
#define EE 1280000
#define DOUT_FINAL 40
#define NB_SCAN 79   // ceil(80000/1024)
#define STRIDE 136   // smem row stride in bf16 elems

// ---------------- scratch (static device globals; no allocs) ----------------
__device__ __nv_bfloat16 g_bfA[(size_t)NN * 64];
__device__ __nv_bfloat16 g_bfB[(size_t)NN * 64];
__device__ __nv_bfloat16 g_wbf[3][64 * 128];   // stacked [Wl^T;Wr^T] as [n][k]
__device__ float g_bias[3][64];
__device__ int   g_deg[NN];
__device__ float g_deginv[NN];
__device__ int   g_rowstart[NN + 1];
__device__ int   g_cursor[NN];
__device__ int   g_bsum[NB_SCAN];
__device__ int   g_csr[EE];
__device__ float g_acc[2];

// ---------------- preamble ----------------
// zero deg/acc + weight/bias -> bf16 stacked (independent work, one kernel)
__global__ void k_zero(const float* __restrict__ Wl0, const float* __restrict__ bl0,
                       const float* __restrict__ Wr0, const float* __restrict__ br0,
                       const float* __restrict__ Wl1, const float* __restrict__ bl1,
                       const float* __restrict__ Wr1, const float* __restrict__ br1,
                       const float* __restrict__ Wl2, const float* __restrict__ bl2,
                       const float* __restrict__ Wr2, const float* __restrict__ br2) {
    int i = blockIdx.x * blockDim.x + threadIdx.x;   // 80,128 threads
    if (i < NN) g_deg[i] = 0;
    if (i < 2)  g_acc[i] = 0.f;
    if (i < 3 * 64 * 128) {
        int l = i >> 13, r = i & 8191, n = r >> 7, k = r & 127;
        float w = 0.f;
        if (l == 0)      w = (k < 64) ? __ldg(Wl0 + n * 64 + k) : __ldg(Wr0 + n * 64 + k - 64);
        else if (l == 1) w = (k < 64) ? __ldg(Wl1 + n * 64 + k) : __ldg(Wr1 + n * 64 + k - 64);
        else if (n < DOUT_FINAL)
                         w = (k < 64) ? __ldg(Wl2 + n * 64 + k) : __ldg(Wr2 + n * 64 + k - 64);
        g_wbf[l][n * 128 + k] = __float2bfloat16(w);
    }
    if (i < 3 * 64) {
        int l = i >> 6, n = i & 63;
        float b = 0.f;
        if (l == 0)      b = __ldg(bl0 + n) + __ldg(br0 + n);
        else if (l == 1) b = __ldg(bl1 + n) + __ldg(br1 + n);
        else if (n < DOUT_FINAL) b = __ldg(bl2 + n) + __ldg(br2 + n);
        g_bias[l][n] = b;
    }
}

__global__ void k_count(const int* __restrict__ dst) {
    int e = blockIdx.x * blockDim.x + threadIdx.x;
    if (e < EE) atomicAdd(&g_deg[__ldg(dst + e)], 1);
}

__global__ void __launch_bounds__(1024) k_scan1() {
    __shared__ int s[1024];
    int t = threadIdx.x;
    int i = blockIdx.x * 1024 + t;
    int v = (i < NN) ? g_deg[i] : 0;
    s[t] = v;
    __syncthreads();
    #pragma unroll
    for (int o = 1; o < 1024; o <<= 1) {
        int u = (t >= o) ? s[t - o] : 0;
        __syncthreads();
        s[t] += u;
        __syncthreads();
    }
    if (i < NN) g_rowstart[i] = s[t] - v;        // exclusive, chunk-local
    if (t == 1023) g_bsum[blockIdx.x] = s[t];
}

// per-block chunk-offset reduction + finalize
__global__ void __launch_bounds__(256) k_scan3() {
    __shared__ int s_off;
    int chunk = blockIdx.x >> 2;
    if (threadIdx.x < 32) {
        int v = 0;
        for (int b = threadIdx.x; b < chunk; b += 32) v += g_bsum[b];
        #pragma unroll
        for (int o = 16; o > 0; o >>= 1) v += __shfl_down_sync(0xffffffffu, v, o);
        if (threadIdx.x == 0) s_off = v;
    }
    __syncthreads();
    int i = blockIdx.x * 256 + threadIdx.x;
    if (i < NN) {
        int rs = g_rowstart[i] + s_off;
        g_rowstart[i] = rs;
        g_cursor[i]   = rs;
        int d = g_deg[i];
        g_deginv[i] = (d > 0) ? 1.f / (float)d : 0.f;
    }
    if (i == 0) g_rowstart[NN] = EE;
}

// fused: CSR slot-scatter + x -> bf16 (both exactly 1,280,000 work items)
__global__ void k_build(const int* __restrict__ dst, const int* __restrict__ src,
                        const float* __restrict__ x) {
    int i = blockIdx.x * blockDim.x + threadIdx.x;   // 1,280,000
    if (i < EE) {
        int d = __ldg(dst + i);
        int slot = atomicAdd(&g_cursor[d], 1);
        g_csr[slot] = __ldg(src + i);
    }
    if (i < NN * 16) {
        float4 v = __ldg((const float4*)x + i);
        __nv_bfloat162 a = __floats2bfloat162_rn(v.x, v.y);
        __nv_bfloat162 b = __floats2bfloat162_rn(v.z, v.w);
        uint2 u;
        u.x = *(unsigned*)&a; u.y = *(unsigned*)&b;
        ((uint2*)g_bfA)[i] = u;
    }
}

// ---------------- fused layer: bf16 gather + HMMA transform (+loss if LAST) ----
__device__ __forceinline__ void add8(float* a, uint4 u) {
    float2 p0 = __bfloat1622float2(*(__nv_bfloat162*)&u.x);
    float2 p1 = __bfloat1622float2(*(__nv_bfloat162*)&u.y);
    float2 p2 = __bfloat1622float2(*(__nv_bfloat162*)&u.z);
    float2 p3 = __bfloat1622float2(*(__nv_bfloat162*)&u.w);
    a[0] += p0.x; a[1] += p0.y; a[2] += p1.x; a[3] += p1.y;
    a[4] += p2.x; a[5] += p2.y; a[6] += p3.x; a[7] += p3.y;
}

__device__ __forceinline__ void mma16816(float& c0, float& c1, float& c2, float& c3,
                                         uint32_t a0, uint32_t a1, uint32_t a2, uint32_t a3,
                                         uint32_t b0, uint32_t b1) {
    asm volatile("mma.sync.aligned.m16n8k16.row.col.f32.bf16.bf16.f32 "
                 "{%0,%1,%2,%3}, {%4,%5,%6,%7}, {%8,%9}, {%0,%1,%2,%3};"
                 : "+f"(c0), "+f"(c1), "+f"(c2), "+f"(c3)
                 : "r"(a0), "r"(a1), "r"(a2), "r"(a3), "r"(b0), "r"(b1));
}

template<bool RELU, bool LAST>
__global__ void __launch_bounds__(256) k_layer(
    const __nv_bfloat16* __restrict__ hbf,   // input activations (bf16)
    const __nv_bfloat16* __restrict__ wbf,   // [64][128] stacked weights
    const float* __restrict__ bias,          // [64] bl+br
    __nv_bfloat16* __restrict__ outbf,       // next-layer activations (if !LAST)
    const int* __restrict__ y,               // labels (if LAST)
    const int* __restrict__ mask)            // train mask (if LAST)
{
    __shared__ __nv_bfloat16 s_act[64 * STRIDE];  // [node][k]  k<64 aggr, k>=64 self
    __shared__ __nv_bfloat16 s_w[64 * STRIDE];    // [n][k]; reused as float logits in LAST
    __shared__ float s_b[64];

    const int t  = threadIdx.x;
    const int nb = blockIdx.x * 64;

    // stage weights (uint4 = 8 bf16)
    #pragma unroll
    for (int idx = t; idx < 1024; idx += 256) {
        int n = idx >> 4, c = idx & 15;
        *(uint4*)(s_w + n * STRIDE + c * 8) = __ldg((const uint4*)(wbf + n * 128) + c);
    }
    if (t < 64) s_b[t] = __ldg(bias + t);

    // stage self rows into k = 64..127
    #pragma unroll
    for (int idx = t; idx < 512; idx += 256) {
        int n = idx >> 3, c = idx & 7;
        *(uint4*)(s_act + n * STRIDE + 64 + c * 8) =
            __ldg((const uint4*)(hbf + (size_t)(nb + n) * 64) + c);
    }

    // gather: warp w -> nodes w*8..w*8+7; quarter-warp per neighbor
    {
        const int w    = t >> 5;
        const int lane = t & 31;
        const int q    = lane >> 3;
        const int d8   = lane & 7;
        for (int i = 0; i < 8; ++i) {
            int nl = w * 8 + i;
            int gn = nb + nl;
            int s0 = __ldg(g_rowstart + gn);
            int s1 = __ldg(g_rowstart + gn + 1);
            float a[8] = {0.f, 0.f, 0.f, 0.f, 0.f, 0.f, 0.f, 0.f};
            int j = s0 + q;
            while (j + 4 < s1) {
                int i0 = __ldg(g_csr + j);
                int i1 = __ldg(g_csr + j + 4);
                uint4 u0 = __ldg((const uint4*)(hbf + (size_t)i0 * 64) + d8);
                uint4 u1 = __ldg((const uint4*)(hbf + (size_t)i1 * 64) + d8);
                add8(a, u0);
                add8(a, u1);
                j += 8;
            }
            if (j < s1) {
                int i0 = __ldg(g_csr + j);
                uint4 u0 = __ldg((const uint4*)(hbf + (size_t)i0 * 64) + d8);
                add8(a, u0);
            }
            #pragma unroll
            for (int v = 0; v < 8; ++v) a[v] += __shfl_xor_sync(0xffffffffu, a[v], 8);
            #pragma unroll
            for (int v = 0; v < 8; ++v) a[v] += __shfl_xor_sync(0xffffffffu, a[v], 16);
            if (q == 0) {
                float di = __ldg(g_deginv + gn);
                __nv_bfloat162 p0 = __floats2bfloat162_rn(a[0] * di, a[1] * di);
                __nv_bfloat162 p1 = __floats2bfloat162_rn(a[2] * di, a[3] * di);
                __nv_bfloat162 p2 = __floats2bfloat162_rn(a[4] * di, a[5] * di);
                __nv_bfloat162 p3 = __floats2bfloat162_rn(a[6] * di, a[7] * di);
                uint4 u;
                u.x = *(unsigned*)&p0; u.y = *(unsigned*)&p1;
                u.z = *(unsigned*)&p2; u.w = *(unsigned*)&p3;
                *(uint4*)(s_act + nl * STRIDE + d8 * 8) = u;
            }
        }
    }
    __syncthreads();

    // HMMA: warp -> m16 x n32 tile; 8 warps cover 64x64
    {
        const int w    = t >> 5;
        const int lane = t & 31;
        const int mw = (w & 3) * 16;
        const int nw = (w >> 2) * 32;
        const int g  = lane >> 2;
        const int tg = lane & 3;

        float c[4][4];
        #pragma unroll
        for (int nt = 0; nt < 4; ++nt) {
            int n0 = nw + nt * 8 + 2 * tg;
            c[nt][0] = s_b[n0]; c[nt][1] = s_b[n0 + 1];
            c[nt][2] = c[nt][0]; c[nt][3] = c[nt][1];
        }

        #pragma unroll
        for (int kk = 0; kk < 8; ++kk) {
            int k0 = kk * 16;
            const __nv_bfloat16* pa = s_act + (mw + g) * STRIDE + k0 + 2 * tg;
            uint32_t a0 = *(const uint32_t*)pa;
            uint32_t a1 = *(const uint32_t*)(pa + 8 * STRIDE);
            uint32_t a2 = *(const uint32_t*)(pa + 8);
            uint32_t a3 = *(const uint32_t*)(pa + 8 * STRIDE + 8);
            #pragma unroll
            for (int nt = 0; nt < 4; ++nt) {
                const __nv_bfloat16* pb = s_w + (nw + nt * 8 + g) * STRIDE + k0 + 2 * tg;
                uint32_t b0 = *(const uint32_t*)pb;
                uint32_t b1 = *(const uint32_t*)(pb + 8);
                mma16816(c[nt][0], c[nt][1], c[nt][2], c[nt][3], a0, a1, a2, a3, b0, b1);
            }
        }

        if (!LAST) {
            // epilogue: relu + bf16 write
            #pragma unroll
            for (int nt = 0; nt < 4; ++nt) {
                int n0 = nw + nt * 8 + 2 * tg;
                int m0 = nb + mw + g;
                float v0 = c[nt][0], v1 = c[nt][1], v2 = c[nt][2], v3 = c[nt][3];
                if (RELU) {
                    v0 = fmaxf(v0, 0.f); v1 = fmaxf(v1, 0.f);
                    v2 = fmaxf(v2, 0.f); v3 = fmaxf(v3, 0.f);
                }
                __nv_bfloat162 p0 = __floats2bfloat162_rn(v0, v1);
                __nv_bfloat162 p1 = __floats2bfloat162_rn(v2, v3);
                *(__nv_bfloat162*)(outbf + (size_t)m0 * 64 + n0) = p0;
                *(__nv_bfloat162*)(outbf + (size_t)(m0 + 8) * 64 + n0) = p1;
            }
        } else {
            // epilogue: logits -> smem (overlay dead weight tile), then loss
            __syncthreads();                       // all warps done reading s_w
            float* lf = (float*)s_w;               // [64][41] floats = 10,496 B
            #pragma unroll
            for (int nt = 0; nt < 4; ++nt) {
                int n0 = nw + nt * 8 + 2 * tg;
                if (n0 < DOUT_FINAL) {
                    lf[(mw + g) * 41 + n0]         = c[nt][0];
                    lf[(mw + g) * 41 + n0 + 1]     = c[nt][1];
                    lf[(mw + g + 8) * 41 + n0]     = c[nt][2];
                    lf[(mw + g + 8) * 41 + n0 + 1] = c[nt][3];
                }
            }
            __syncthreads();
            if (t < 64) {                          // warps 0,1 whole
                float nll = 0.f, mv = 0.f;
                int gn = nb + t;
                if (__ldg(mask + gn) != 0) {
                    const float* l = lf + t * 41;
                    float mx = l[0];
                    #pragma unroll
                    for (int d = 1; d < DOUT_FINAL; ++d) mx = fmaxf(mx, l[d]);
                    float s = 0.f;
                    #pragma unroll
                    for (int d = 0; d < DOUT_FINAL; ++d) s += expf(l[d] - mx);
                    nll = mx + logf(s) - l[__ldg(y + gn)];
                    mv = 1.f;
                }
                #pragma unroll
                for (int o = 16; o > 0; o >>= 1) {
                    nll += __shfl_down_sync(0xffffffffu, nll, o);
                    mv  += __shfl_down_sync(0xffffffffu, mv, o);
                }
                if ((t & 31) == 0) {
                    atomicAdd(&g_acc[0], nll);
                    atomicAdd(&g_acc[1], mv);
                }
            }
        }
    }
}

__global__ void k_final(float* out) {
    out[0] = g_acc[0] / fmaxf(g_acc[1], 1.f);
}

// ---------------- launcher ----------------
extern "C" void kernel_launch(void* const* d_in, const int* in_sizes, int n_in,
                              void* d_out, int out_size) {
    const float* x   = (const float*)d_in[0];
    const float* Wl0 = (const float*)d_in[1];
    const float* bl0 = (const float*)d_in[2];
    const float* Wr0 = (const float*)d_in[3];
    const float* br0 = (const float*)d_in[4];
    const float* Wl1 = (const float*)d_in[5];
    const float* bl1 = (const float*)d_in[6];
    const float* Wr1 = (const float*)d_in[7];
    const float* br1 = (const float*)d_in[8];
    const float* Wl2 = (const float*)d_in[9];
    const float* bl2 = (const float*)d_in[10];
    const float* Wr2 = (const float*)d_in[11];
    const float* br2 = (const float*)d_in[12];
    const int*   ei  = (const int*)d_in[13];
    const int*   y   = (const int*)d_in[14];
    const int*   msk = (const int*)d_in[15];
    const int* dst = ei;        // edge_index[0]
    const int* src = ei + EE;   // edge_index[1]

    __nv_bfloat16 *bfA, *bfB, *wbf;
    float *bias;
    cudaGetSymbolAddress((void**)&bfA, g_bfA);
    cudaGetSymbolAddress((void**)&bfB, g_bfB);
    cudaGetSymbolAddress((void**)&wbf, g_wbf);
    cudaGetSymbolAddress((void**)&bias, g_bias);

    // preamble
    k_zero<<<(NN + 255) / 256, 256>>>(Wl0, bl0, Wr0, br0, Wl1, bl1, Wr1, br1, Wl2, bl2, Wr2, br2);
    k_count<<<5000, 256>>>(dst);
    k_scan1<<<NB_SCAN, 1024>>>();
    k_scan3<<<(NN + 255) / 256, 256>>>();
    k_build<<<5000, 256>>>(dst, src, x);

    const int blocks = NN / 64;   // 1250

    // layer 0: bfA -> bfB
    k_layer<true, false><<<blocks, 256>>>(bfA, wbf, bias, bfB, nullptr, nullptr);
    // layer 1: bfB -> bfA
    k_layer<true, false><<<blocks, 256>>>(bfB, wbf + 64 * 128, bias + 64, bfA, nullptr, nullptr);
    // layer 2: bfA -> loss accumulators (loss fused)
    k_layer<false, true><<<blocks, 256>>>(bfA, wbf + 2 * 64 * 128, bias + 128, nullptr, y, msk);

    k_final<<<1, 1>>>((float*)d_out);
}